// round 6
// baseline (speedup 1.0000x reference)
#include <cuda_runtime.h>
#include <math.h>

// Problem constants
#define BB 8
#define CC 512
#define NN 4096   // H*W
#define DD 32     // C / R

// Scratch (allocation-free rule: __device__ globals)
__device__ float g_q[BB * DD * NN];                    // 4 MB
__device__ float g_k[BB * DD * NN];                    // 4 MB
__device__ float g_v[BB * CC * NN];                    // 64 MB
__device__ float g_P[(size_t)BB * NN * NN];            // 512 MB  (unnormalized exp(logits))
__device__ float g_rs[BB * NN];                        // row sums

// ---------------------------------------------------------------------------
// Generic split-tile SGEMM: C[m][n] = sum_k A[m][k] * B[k][n]   (AT=false)
//                         or       = sum_k A[k][m] * B[k][n]    (AT=true)
// All of M, N divisible by BM, BN; K divisible by BK (guaranteed by shapes).
// EXP: apply __expf in epilogue (for unnormalized softmax numerator).
// ---------------------------------------------------------------------------
template <int BM, int BN, int BK, int TM, int TN, bool AT, bool EXP>
__global__ void __launch_bounds__((BM / TM) * (BN / TN))
sgemm_tpl(const float* __restrict__ A, const float* __restrict__ B,
          float* __restrict__ C, int M, int N, int K,
          long long sA, long long sB, long long sC)
{
    constexpr int THREADS = (BM / TM) * (BN / TN);
    constexpr int PAD = 4;
    __shared__ float As[BK][BM + PAD];
    __shared__ float Bs[BK][BN];

    const long long bz = blockIdx.z;
    A += bz * sA;
    B += bz * sB;
    C += bz * sC;

    const int bm = blockIdx.y * BM;
    const int bn = blockIdx.x * BN;
    const int tid = threadIdx.x;

    constexpr int RX = BN / TN;          // threads along n
    const int tx = tid % RX;
    const int ty = tid / RX;
    const int tn0 = tx * (TN / 2);       // split-tile: cols [tn0, BN/2+tn0)
    const int tm0 = ty * (TM / 2);       // rows [tm0, BM/2+tm0)

    float acc[TM][TN];
#pragma unroll
    for (int i = 0; i < TM; i++)
#pragma unroll
        for (int j = 0; j < TN; j++) acc[i][j] = 0.f;

    for (int k0 = 0; k0 < K; k0 += BK) {
        // ---- load A tile into As[k][m] ----
        if (AT) {
            constexpr int NV = BM * BK / 4;          // float4 count
#pragma unroll
            for (int r = 0; r < NV / THREADS; r++) {
                int i = r * THREADS + tid;
                int kk = i / (BM / 4);
                int mv = i % (BM / 4);
                float4 v = *reinterpret_cast<const float4*>(
                    A + (long long)(k0 + kk) * M + bm + mv * 4);
                As[kk][mv * 4 + 0] = v.x;
                As[kk][mv * 4 + 1] = v.y;
                As[kk][mv * 4 + 2] = v.z;
                As[kk][mv * 4 + 3] = v.w;
            }
        } else {
            constexpr int NE = BM * BK;              // scalar, transposed store
#pragma unroll
            for (int r = 0; r < NE / THREADS; r++) {
                int i = r * THREADS + tid;
                int mm = i / BK;
                int kk = i % BK;
                As[kk][mm] = A[(long long)(bm + mm) * K + k0 + kk];
            }
        }
        // ---- load B tile (row-major, float4) ----
        constexpr int NBV = BK * BN / 4;
#pragma unroll
        for (int r = 0; r < NBV / THREADS; r++) {
            int i = r * THREADS + tid;
            int kk = i / (BN / 4);
            int nv = i % (BN / 4);
            float4 v = *reinterpret_cast<const float4*>(
                B + (long long)(k0 + kk) * N + bn + nv * 4);
            *reinterpret_cast<float4*>(&Bs[kk][nv * 4]) = v;
        }
        __syncthreads();

#pragma unroll
        for (int kk = 0; kk < BK; kk++) {
            float ar[TM], br[TN];
#pragma unroll
            for (int i = 0; i < TM / 2; i++) {
                ar[i]          = As[kk][tm0 + i];
                ar[TM / 2 + i] = As[kk][BM / 2 + tm0 + i];
            }
#pragma unroll
            for (int j = 0; j < TN / 2; j++) {
                br[j]          = Bs[kk][tn0 + j];
                br[TN / 2 + j] = Bs[kk][BN / 2 + tn0 + j];
            }
#pragma unroll
            for (int i = 0; i < TM; i++)
#pragma unroll
                for (int j = 0; j < TN; j++)
                    acc[i][j] = fmaf(ar[i], br[j], acc[i][j]);
        }
        __syncthreads();
    }

    // ---- epilogue ----
#pragma unroll
    for (int i = 0; i < TM; i++) {
        int row = bm + ((i < TM / 2) ? (tm0 + i) : (BM / 2 + tm0 + i - TM / 2));
        float* Cr = C + (long long)row * N + bn;
#pragma unroll
        for (int j = 0; j < TN; j++) {
            int col = (j < TN / 2) ? (tn0 + j) : (BN / 2 + tn0 + j - TN / 2);
            float val = acc[i][j];
            if (EXP) val = __expf(val);
            Cr[col] = val;
        }
    }
}

// ---------------------------------------------------------------------------
// Row sums of P: one block per (b, m) row of length NN.
// ---------------------------------------------------------------------------
__global__ void rowsum_k(const float* __restrict__ P, float* __restrict__ rs)
{
    __shared__ float sm[8];
    const float4* row = reinterpret_cast<const float4*>(P + (size_t)blockIdx.x * NN);
    float s = 0.f;
#pragma unroll 4
    for (int i = threadIdx.x; i < NN / 4; i += 256) {
        float4 u = row[i];
        s += (u.x + u.y) + (u.z + u.w);
    }
#pragma unroll
    for (int o = 16; o; o >>= 1) s += __shfl_xor_sync(0xFFFFFFFFu, s, o);
    if ((threadIdx.x & 31) == 0) sm[threadIdx.x >> 5] = s;
    __syncthreads();
    if (threadIdx.x < 8) {
        s = sm[threadIdx.x];
#pragma unroll
        for (int o = 4; o; o >>= 1) s += __shfl_xor_sync(0xFFu, s, o);
        if (threadIdx.x == 0) rs[blockIdx.x] = s;
    }
}

// ---------------------------------------------------------------------------
// Fold softmax denominator into v: v[b][c][m] /= rowsum[b][m]
// ---------------------------------------------------------------------------
__global__ void vscale_k(float* __restrict__ v, const float* __restrict__ rs)
{
    size_t idx = (size_t)blockIdx.x * blockDim.x + threadIdx.x;   // < 8*512*4096
    int m = (int)(idx & (NN - 1));
    int b = (int)(idx >> 21);                                     // / (512*4096)
    v[idx] = v[idx] / rs[b * NN + m];
}

// ---------------------------------------------------------------------------
extern "C" void kernel_launch(void* const* d_in, const int* in_sizes, int n_in,
                              void* d_out, int out_size)
{
    // Identify inputs by element count (robust to metadata ordering):
    // x: 8*512*4096 = 16777216, Wv: 512*512 = 262144, Wq/Wk: 32*512 = 16384 (q first)
    const float* x = nullptr;
    const float* Wq = nullptr;
    const float* Wk = nullptr;
    const float* Wv = nullptr;
    for (int i = 0; i < n_in; i++) {
        int sz = in_sizes[i];
        const float* p = (const float*)d_in[i];
        if (sz == BB * CC * NN)      x = p;
        else if (sz == CC * CC)      Wv = p;
        else if (sz == DD * CC) {
            if (!Wq) Wq = p; else Wk = p;
        }
    }
    float* out = (float*)d_out;

    float *q, *k, *v, *P, *rs;
    cudaGetSymbolAddress((void**)&q,  g_q);
    cudaGetSymbolAddress((void**)&k,  g_k);
    cudaGetSymbolAddress((void**)&v,  g_v);
    cudaGetSymbolAddress((void**)&P,  g_P);
    cudaGetSymbolAddress((void**)&rs, g_rs);

    const long long sX = (long long)CC * NN;   // x / v batch stride
    const long long sQ = (long long)DD * NN;   // q / k batch stride
    const long long sP = (long long)NN * NN;   // P batch stride

    // 1) v = Wv @ x[b]     (M=512, N=4096, K=512)
    sgemm_tpl<128, 128, 8, 8, 8, false, false>
        <<<dim3(NN / 128, CC / 128, BB), 256>>>(Wv, x, v, CC, NN, CC, 0, sX, sX);

    // 2) q = Wq @ x[b], k = Wk @ x[b]   (M=32, N=4096, K=512)
    sgemm_tpl<32, 128, 16, 4, 8, false, false>
        <<<dim3(NN / 128, 1, BB), 128>>>(Wq, x, q, DD, NN, CC, 0, sX, sQ);
    sgemm_tpl<32, 128, 16, 4, 8, false, false>
        <<<dim3(NN / 128, 1, BB), 128>>>(Wk, x, k, DD, NN, CC, 0, sX, sQ);

    // 3) P = exp(q^T @ k)   (M=N=4096, K=32; A stored [K][M] -> AT mode)
    sgemm_tpl<128, 128, 8, 8, 8, true, true>
        <<<dim3(NN / 128, NN / 128, BB), 256>>>(q, k, P, NN, NN, DD, sQ, sQ, sP);

    // 4) rowsums of P, then fold 1/rowsum into v columns
    rowsum_k<<<BB * NN, 256>>>(P, rs);
    vscale_k<<<(BB * CC * NN) / 256, 256>>>(v, rs);

    // 5) out = v' @ P       (M=512, N=4096, K=4096)
    sgemm_tpl<128, 128, 8, 8, 8, false, false>
        <<<dim3(NN / 128, CC / 128, BB), 256>>>(v, P, out, CC, NN, NN, sX, sP, sX);
}

// round 9
// speedup vs baseline: 2.1988x; 2.1988x over previous
#include <cuda_runtime.h>
#include <cstdint>
#include <math.h>

// Problem constants
#define BB 8
#define CC 512
#define NN 4096   // H*W
#define DD 32     // C / R

// Scratch (allocation-free rule: __device__ globals)
__device__ float g_q [BB * DD * NN];                   // q[b][d][n]  4 MB
__device__ float g_k [BB * DD * NN];                   // k[b][d][n]  4 MB
__device__ float g_v [(size_t)BB * CC * NN];           // v[b][c][m]  64 MB
__device__ float g_xT[(size_t)BB * CC * NN];           // xT[b][n][c] 64 MB (tf32-rounded)
__device__ float g_P [(size_t)BB * NN * NN];           // P'[b][n][m] 512 MB (tf32-rounded)
__device__ float g_Wv[CC * CC];                        // Wv tf32-rounded, 1 MB
__device__ float g_rsp[BB * 32 * NN];                  // partial column sums
__device__ float g_rs [BB * NN];                       // rowsum[b][m]

// ============================================================================
// helpers
// ============================================================================
__device__ __forceinline__ uint32_t smem_u32(const void* p) {
    uint32_t a;
    asm("{ .reg .u64 t; cvta.to.shared.u64 t, %1; cvt.u32.u64 %0, t; }"
        : "=r"(a) : "l"(p));
    return a;
}
__device__ __forceinline__ void cpa16(uint32_t dst, const void* src) {
    asm volatile("cp.async.cg.shared.global [%0], [%1], 16;"
                 :: "r"(dst), "l"(src));
}
// Round-to-nearest tf32 (value stays a valid fp32; HW RZ inside MMA is then exact)
__device__ __forceinline__ float rntf32(float f) {
    uint32_t u;
    asm("cvt.rna.tf32.f32 %0, %1;" : "=r"(u) : "f"(f));
    return __uint_as_float(u);
}
__device__ __forceinline__ void mma_tf32(float c[4],
                                         uint32_t a0, uint32_t a1, uint32_t a2, uint32_t a3,
                                         uint32_t b0, uint32_t b1) {
    asm volatile(
        "mma.sync.aligned.m16n8k8.row.col.f32.tf32.tf32.f32 "
        "{%0,%1,%2,%3}, {%4,%5,%6,%7}, {%8,%9}, {%0,%1,%2,%3};"
        : "+f"(c[0]), "+f"(c[1]), "+f"(c[2]), "+f"(c[3])
        : "r"(a0), "r"(a1), "r"(a2), "r"(a3), "r"(b0), "r"(b1));
}

// ============================================================================
// tf32 mma.sync GEMM: C[m][n] = sum_k A[m][k] * B[n][k]
// A: [M][K] row-major, B: [N][K] row-major (both K-contiguous).
// Block tile 128(M) x 256(N) x 32(K); 8 warps, each 64x64.
// Inputs must be pre-rounded to tf32 (RN) by the producers.
// ============================================================================
#define MG_ASTRIDE 36
#define MG_ASZ (128 * MG_ASTRIDE)          // floats
#define MG_BSZ (256 * MG_ASTRIDE)
#define MG_SMEM_BYTES ((2 * MG_ASZ + 2 * MG_BSZ) * 4)   // 110592

__global__ void __launch_bounds__(256)
mma_gemm(const float* __restrict__ A, const float* __restrict__ B,
         float* __restrict__ C, int K,
         long long sA, long long sB, long long sC, int ldc)
{
    extern __shared__ float sm[];
    float* Asm[2] = { sm, sm + MG_ASZ };
    float* Bsm[2] = { sm + 2 * MG_ASZ, sm + 2 * MG_ASZ + MG_BSZ };
    const uint32_t sb = smem_u32(sm);
    const uint32_t aoff[2] = { 0u, (uint32_t)(MG_ASZ * 4) };
    const uint32_t boff[2] = { (uint32_t)(2 * MG_ASZ * 4),
                               (uint32_t)((2 * MG_ASZ + MG_BSZ) * 4) };

    const int tid = threadIdx.x;
    const int lane = tid & 31;
    const int wid = tid >> 5;
    const int g = lane >> 2;       // 0..7
    const int tg = lane & 3;       // 0..3
    const int wm = wid & 1;        // 2 warps along M
    const int wn = wid >> 1;       // 4 warps along N

    const long long bz = blockIdx.z;
    const int bm = blockIdx.y * 128;
    const int bn = blockIdx.x * 256;
    const float* Ag = A + bz * sA + (size_t)bm * K;
    const float* Bg = B + bz * sB + (size_t)bn * K;

    float acc[4][8][4];
#pragma unroll
    for (int mf = 0; mf < 4; mf++)
#pragma unroll
        for (int nf = 0; nf < 8; nf++)
#pragma unroll
            for (int i = 0; i < 4; i++) acc[mf][nf][i] = 0.f;

    const int row = tid >> 3;       // 0..31
    const int k4  = tid & 7;

    auto load_tile = [&](int t, int p) {
        const int k0 = t * 32;
#pragma unroll
        for (int it = 0; it < 4; it++) {
            int r = it * 32 + row;
            cpa16(sb + aoff[p] + (uint32_t)(r * MG_ASTRIDE + k4 * 4) * 4,
                  Ag + (size_t)r * K + k0 + k4 * 4);
        }
#pragma unroll
        for (int it = 0; it < 8; it++) {
            int r = it * 32 + row;
            cpa16(sb + boff[p] + (uint32_t)(r * MG_ASTRIDE + k4 * 4) * 4,
                  Bg + (size_t)r * K + k0 + k4 * 4);
        }
        asm volatile("cp.async.commit_group;");
    };

    const int NT = K / 32;
    load_tile(0, 0);

    for (int t = 0; t < NT; t++) {
        const int p = t & 1;
        if (t + 1 < NT) {
            load_tile(t + 1, p ^ 1);
            asm volatile("cp.async.wait_group 1;");
        } else {
            asm volatile("cp.async.wait_group 0;");
        }
        __syncthreads();

        const float* Ab = Asm[p];
        const float* Bb = Bsm[p];
#pragma unroll
        for (int ks = 0; ks < 4; ks++) {
            const int k0 = ks * 8 + tg;
            uint32_t a[4][4], b[8][2];
#pragma unroll
            for (int mf = 0; mf < 4; mf++) {
                int m = wm * 64 + mf * 16 + g;
                a[mf][0] = __float_as_uint(Ab[m * MG_ASTRIDE + k0]);
                a[mf][1] = __float_as_uint(Ab[(m + 8) * MG_ASTRIDE + k0]);
                a[mf][2] = __float_as_uint(Ab[m * MG_ASTRIDE + k0 + 4]);
                a[mf][3] = __float_as_uint(Ab[(m + 8) * MG_ASTRIDE + k0 + 4]);
            }
#pragma unroll
            for (int nf = 0; nf < 8; nf++) {
                int n = wn * 64 + nf * 8 + g;
                b[nf][0] = __float_as_uint(Bb[n * MG_ASTRIDE + k0]);
                b[nf][1] = __float_as_uint(Bb[n * MG_ASTRIDE + k0 + 4]);
            }
#pragma unroll
            for (int mf = 0; mf < 4; mf++)
#pragma unroll
                for (int nf = 0; nf < 8; nf++)
                    mma_tf32(acc[mf][nf],
                             a[mf][0], a[mf][1], a[mf][2], a[mf][3],
                             b[nf][0], b[nf][1]);
        }
        __syncthreads();
    }

    // Epilogue: float2 stores
    float* Cb = C + bz * sC;
#pragma unroll
    for (int mf = 0; mf < 4; mf++) {
        const int r0 = bm + wm * 64 + mf * 16 + g;
        const int r1 = r0 + 8;
#pragma unroll
        for (int nf = 0; nf < 8; nf++) {
            const int c = bn + wn * 64 + nf * 8 + tg * 2;
            *reinterpret_cast<float2*>(&Cb[(size_t)r0 * ldc + c]) =
                make_float2(acc[mf][nf][0], acc[mf][nf][1]);
            *reinterpret_cast<float2*>(&Cb[(size_t)r1 * ldc + c]) =
                make_float2(acc[mf][nf][2], acc[mf][nf][3]);
        }
    }
}

// ============================================================================
// fp32 split-tile SGEMM (q/k projections and exp-logits).
// EXP epilogue additionally rounds the result to tf32 (RN) — P feeds the
// tf32 out-GEMM and must be exactly representable.
// ============================================================================
template <int BM, int BN, int BK, int TM, int TN, bool AT, bool EXP>
__global__ void __launch_bounds__((BM / TM) * (BN / TN))
sgemm_tpl(const float* __restrict__ A, const float* __restrict__ B,
          float* __restrict__ C, int M, int N, int K,
          long long sA, long long sB, long long sC)
{
    constexpr int THREADS = (BM / TM) * (BN / TN);
    constexpr int PAD = 4;
    __shared__ float As[BK][BM + PAD];
    __shared__ float Bs[BK][BN];

    const long long bz = blockIdx.z;
    A += bz * sA; B += bz * sB; C += bz * sC;

    const int bm = blockIdx.y * BM;
    const int bn = blockIdx.x * BN;
    const int tid = threadIdx.x;

    constexpr int RX = BN / TN;
    const int tx = tid % RX;
    const int ty = tid / RX;
    const int tn0 = tx * (TN / 2);
    const int tm0 = ty * (TM / 2);

    float acc[TM][TN];
#pragma unroll
    for (int i = 0; i < TM; i++)
#pragma unroll
        for (int j = 0; j < TN; j++) acc[i][j] = 0.f;

    for (int k0 = 0; k0 < K; k0 += BK) {
        if (AT) {
            constexpr int NV = BM * BK / 4;
#pragma unroll
            for (int r = 0; r < NV / THREADS; r++) {
                int i = r * THREADS + tid;
                int kk = i / (BM / 4);
                int mv = i % (BM / 4);
                float4 v = *reinterpret_cast<const float4*>(
                    A + (long long)(k0 + kk) * M + bm + mv * 4);
                As[kk][mv * 4 + 0] = v.x; As[kk][mv * 4 + 1] = v.y;
                As[kk][mv * 4 + 2] = v.z; As[kk][mv * 4 + 3] = v.w;
            }
        } else {
            constexpr int NE = BM * BK;
#pragma unroll
            for (int r = 0; r < NE / THREADS; r++) {
                int i = r * THREADS + tid;
                int mm = i / BK;
                int kk = i % BK;
                As[kk][mm] = A[(long long)(bm + mm) * K + k0 + kk];
            }
        }
        constexpr int NBV = BK * BN / 4;
#pragma unroll
        for (int r = 0; r < NBV / THREADS; r++) {
            int i = r * THREADS + tid;
            int kk = i / (BN / 4);
            int nv = i % (BN / 4);
            float4 v = *reinterpret_cast<const float4*>(
                B + (long long)(k0 + kk) * N + bn + nv * 4);
            *reinterpret_cast<float4*>(&Bs[kk][nv * 4]) = v;
        }
        __syncthreads();

#pragma unroll
        for (int kk = 0; kk < BK; kk++) {
            float ar[TM], br[TN];
#pragma unroll
            for (int i = 0; i < TM / 2; i++) {
                ar[i]          = As[kk][tm0 + i];
                ar[TM / 2 + i] = As[kk][BM / 2 + tm0 + i];
            }
#pragma unroll
            for (int j = 0; j < TN / 2; j++) {
                br[j]          = Bs[kk][tn0 + j];
                br[TN / 2 + j] = Bs[kk][BN / 2 + tn0 + j];
            }
#pragma unroll
            for (int i = 0; i < TM; i++)
#pragma unroll
                for (int j = 0; j < TN; j++)
                    acc[i][j] = fmaf(ar[i], br[j], acc[i][j]);
        }
        __syncthreads();
    }

#pragma unroll
    for (int i = 0; i < TM; i++) {
        int row = bm + ((i < TM / 2) ? (tm0 + i) : (BM / 2 + tm0 + i - TM / 2));
        float* Cr = C + (long long)row * N + bn;
#pragma unroll
        for (int j = 0; j < TN; j++) {
            int col = (j < TN / 2) ? (tn0 + j) : (BN / 2 + tn0 + j - TN / 2);
            float val = acc[i][j];
            if (EXP) val = rntf32(__expf(val));
            Cr[col] = val;
        }
    }
}

// ============================================================================
// x[b][c][n] -> xT[b][n][c], rounded to tf32 (feeds the v-proj tf32 GEMM)
// ============================================================================
__global__ void transpose_k(const float* __restrict__ x, float* __restrict__ xT)
{
    __shared__ float t[32][33];
    const size_t base = (size_t)blockIdx.z * CC * NN;
    const int c0 = blockIdx.y * 32;
    const int n0 = blockIdx.x * 32;
    const float* xi = x + base;
    float* xo = xT + base;
#pragma unroll
    for (int i = threadIdx.y; i < 32; i += 8)
        t[i][threadIdx.x] = xi[(size_t)(c0 + i) * NN + n0 + threadIdx.x];
    __syncthreads();
#pragma unroll
    for (int i = threadIdx.y; i < 32; i += 8)
        xo[(size_t)(n0 + i) * CC + c0 + threadIdx.x] = rntf32(t[threadIdx.x][i]);
}

// Wv -> g_Wv rounded to tf32
__global__ void roundw_k(const float* __restrict__ W, float* __restrict__ Wo)
{
    int i = blockIdx.x * 256 + threadIdx.x;
    Wo[i] = rntf32(W[i]);
}

// ============================================================================
// Column sums of P' (= softmax rowsums): rs[b][m] = sum_n P'[b][n][m]
// ============================================================================
__global__ void colsum_part(const float* __restrict__ P, float* __restrict__ rsp)
{
    const int m = blockIdx.x * 256 + threadIdx.x;
    const int j = blockIdx.y;
    const int b = blockIdx.z;
    const float* p = P + (size_t)b * NN * NN + (size_t)j * 128 * NN + m;
    float s = 0.f;
#pragma unroll 4
    for (int n = 0; n < 128; n++) s += p[(size_t)n * NN];
    rsp[((size_t)b * 32 + j) * NN + m] = s;
}

__global__ void colsum_final(const float* __restrict__ rsp, float* __restrict__ rs)
{
    const int m = blockIdx.x * 256 + threadIdx.x;
    const int b = blockIdx.y;
    float s = 0.f;
#pragma unroll
    for (int j = 0; j < 32; j++) s += rsp[((size_t)b * 32 + j) * NN + m];
    rs[b * NN + m] = s;
}

// v[b][c][m] = rntf32(v / rs[b][m])   (feeds the tf32 out-GEMM)
__global__ void vscale_k(float* __restrict__ v, const float* __restrict__ rs)
{
    size_t idx = (size_t)blockIdx.x * blockDim.x + threadIdx.x;
    int m = (int)(idx & (NN - 1));
    int b = (int)(idx >> 21);
    v[idx] = rntf32(v[idx] / rs[b * NN + m]);
}

// ============================================================================
extern "C" void kernel_launch(void* const* d_in, const int* in_sizes, int n_in,
                              void* d_out, int out_size)
{
    const float* x = nullptr;
    const float* Wq = nullptr;
    const float* Wk = nullptr;
    const float* Wv = nullptr;
    for (int i = 0; i < n_in; i++) {
        int sz = in_sizes[i];
        const float* p = (const float*)d_in[i];
        if (sz == BB * CC * NN)      x = p;
        else if (sz == CC * CC)      Wv = p;
        else if (sz == DD * CC) { if (!Wq) Wq = p; else Wk = p; }
    }
    float* out = (float*)d_out;

    float *q, *k, *v, *xT, *P, *Wvr, *rsp, *rs;
    cudaGetSymbolAddress((void**)&q,   g_q);
    cudaGetSymbolAddress((void**)&k,   g_k);
    cudaGetSymbolAddress((void**)&v,   g_v);
    cudaGetSymbolAddress((void**)&xT,  g_xT);
    cudaGetSymbolAddress((void**)&P,   g_P);
    cudaGetSymbolAddress((void**)&Wvr, g_Wv);
    cudaGetSymbolAddress((void**)&rsp, g_rsp);
    cudaGetSymbolAddress((void**)&rs,  g_rs);

    cudaFuncSetAttribute(mma_gemm, cudaFuncAttributeMaxDynamicSharedMemorySize,
                         MG_SMEM_BYTES);

    const long long sX = (long long)CC * NN;   // x / xT / v batch stride
    const long long sQ = (long long)DD * NN;   // q / k batch stride
    const long long sP = (long long)NN * NN;   // P batch stride

    // 0) Wv rounded to tf32
    roundw_k<<<(CC * CC) / 256, 256>>>(Wv, Wvr);

    // 1) xT = transpose(x) per batch, tf32-rounded: [n][c]
    transpose_k<<<dim3(NN / 32, CC / 32, BB), dim3(32, 8)>>>(x, xT);

    // 2) v[c][m] = sum_ch Wv[c][ch] * xT[m][ch]   (tf32 mma.sync)
    mma_gemm<<<dim3(NN / 256, CC / 128, BB), 256, MG_SMEM_BYTES>>>(
        Wvr, xT, v, CC, 0, sX, sX, NN);

    // 3) q = Wq @ x, k = Wk @ x   (fp32, [d][n])
    sgemm_tpl<32, 128, 16, 4, 8, false, false>
        <<<dim3(NN / 128, 1, BB), 128>>>(Wq, x, q, DD, NN, CC, 0, sX, sQ);
    sgemm_tpl<32, 128, 16, 4, 8, false, false>
        <<<dim3(NN / 128, 1, BB), 128>>>(Wk, x, k, DD, NN, CC, 0, sX, sQ);

    // 4) P'[n][m] = exp(sum_d k[d][n] q[d][m])   (fp32, AT mode; tf32-rounded out)
    sgemm_tpl<128, 128, 8, 8, 8, true, true>
        <<<dim3(NN / 128, NN / 128, BB), 256>>>(k, q, P, NN, NN, DD, sQ, sQ, sP);

    // 5) rowsums (column sums of P'), then fold 1/rowsum into v (tf32-rounded)
    colsum_part<<<dim3(NN / 256, 32, BB), 256>>>(P, rsp);
    colsum_final<<<dim3(NN / 256, BB), 256>>>(rsp, rs);
    vscale_k<<<((size_t)BB * CC * NN) / 256, 256>>>(v, rs);

    // 6) out[c][n] = sum_m v[c][m] * P'[n][m]   (tf32 mma.sync)
    mma_gemm<<<dim3(NN / 256, CC / 128, BB), 256, MG_SMEM_BYTES>>>(
        v, P, out, NN, sX, sP, sX, NN);
}

// round 10
// speedup vs baseline: 2.4281x; 1.1043x over previous
#include <cuda_runtime.h>
#include <cstdint>
#include <math.h>

// Problem constants
#define BB 8
#define CC 512
#define NN 4096   // H*W
#define DD 32     // C / R

// Scratch (allocation-free rule: __device__ globals)
__device__ float g_qk[BB * 2 * DD * NN];               // [b][64][n]: rows 0-31=q, 32-63=k (8 MB)
__device__ float g_v [(size_t)BB * CC * NN];           // v[b][c][m]  64 MB
__device__ float g_xT[(size_t)BB * CC * NN];           // xT[b][n][c] 64 MB (tf32-rounded)
__device__ float g_P [(size_t)BB * NN * NN];           // P'[b][n][m] 512 MB (tf32-rounded)
__device__ float g_Wv[CC * CC];                        // Wv tf32-rounded, 1 MB
__device__ float g_Wqk[2 * DD * CC];                   // concat [Wq; Wk], 128 KB
__device__ float g_rsp[BB * 32 * NN];                  // partial column sums
__device__ float g_rs [BB * NN];                       // rowsum[b][m]

// ============================================================================
// helpers
// ============================================================================
__device__ __forceinline__ uint32_t smem_u32(const void* p) {
    uint32_t a;
    asm("{ .reg .u64 t; cvta.to.shared.u64 t, %1; cvt.u32.u64 %0, t; }"
        : "=r"(a) : "l"(p));
    return a;
}
__device__ __forceinline__ void cpa16(uint32_t dst, const void* src) {
    asm volatile("cp.async.cg.shared.global [%0], [%1], 16;"
                 :: "r"(dst), "l"(src));
}
// Round-to-nearest tf32 (value stays a valid fp32; HW RZ inside MMA is then exact)
__device__ __forceinline__ float rntf32(float f) {
    uint32_t u;
    asm("cvt.rna.tf32.f32 %0, %1;" : "=r"(u) : "f"(f));
    return __uint_as_float(u);
}
__device__ __forceinline__ void mma_tf32(float c[4],
                                         uint32_t a0, uint32_t a1, uint32_t a2, uint32_t a3,
                                         uint32_t b0, uint32_t b1) {
    asm volatile(
        "mma.sync.aligned.m16n8k8.row.col.f32.tf32.tf32.f32 "
        "{%0,%1,%2,%3}, {%4,%5,%6,%7}, {%8,%9}, {%0,%1,%2,%3};"
        : "+f"(c[0]), "+f"(c[1]), "+f"(c[2]), "+f"(c[3])
        : "r"(a0), "r"(a1), "r"(a2), "r"(a3), "r"(b0), "r"(b1));
}

// ============================================================================
// tf32 mma.sync GEMM: C[m][n] = sum_k A[m][k] * B[n][k]
// Block tile 128(M) x 256(N) x 32(K); 8 warps, each 64x64.
// Inputs must be pre-rounded to tf32 (RN) by the producers.
// ============================================================================
#define MG_ASTRIDE 36
#define MG_ASZ (128 * MG_ASTRIDE)
#define MG_BSZ (256 * MG_ASTRIDE)
#define MG_SMEM_BYTES ((2 * MG_ASZ + 2 * MG_BSZ) * 4)   // 110592

__global__ void __launch_bounds__(256)
mma_gemm(const float* __restrict__ A, const float* __restrict__ B,
         float* __restrict__ C, int K,
         long long sA, long long sB, long long sC, int ldc)
{
    extern __shared__ float sm[];
    float* Asm[2] = { sm, sm + MG_ASZ };
    float* Bsm[2] = { sm + 2 * MG_ASZ, sm + 2 * MG_ASZ + MG_BSZ };
    const uint32_t sb = smem_u32(sm);
    const uint32_t aoff[2] = { 0u, (uint32_t)(MG_ASZ * 4) };
    const uint32_t boff[2] = { (uint32_t)(2 * MG_ASZ * 4),
                               (uint32_t)((2 * MG_ASZ + MG_BSZ) * 4) };

    const int tid = threadIdx.x;
    const int lane = tid & 31;
    const int wid = tid >> 5;
    const int g = lane >> 2;
    const int tg = lane & 3;
    const int wm = wid & 1;
    const int wn = wid >> 1;

    const long long bz = blockIdx.z;
    const int bm = blockIdx.y * 128;
    const int bn = blockIdx.x * 256;
    const float* Ag = A + bz * sA + (size_t)bm * K;
    const float* Bg = B + bz * sB + (size_t)bn * K;

    float acc[4][8][4];
#pragma unroll
    for (int mf = 0; mf < 4; mf++)
#pragma unroll
        for (int nf = 0; nf < 8; nf++)
#pragma unroll
            for (int i = 0; i < 4; i++) acc[mf][nf][i] = 0.f;

    const int row = tid >> 3;
    const int k4  = tid & 7;

    auto load_tile = [&](int t, int p) {
        const int k0 = t * 32;
#pragma unroll
        for (int it = 0; it < 4; it++) {
            int r = it * 32 + row;
            cpa16(sb + aoff[p] + (uint32_t)(r * MG_ASTRIDE + k4 * 4) * 4,
                  Ag + (size_t)r * K + k0 + k4 * 4);
        }
#pragma unroll
        for (int it = 0; it < 8; it++) {
            int r = it * 32 + row;
            cpa16(sb + boff[p] + (uint32_t)(r * MG_ASTRIDE + k4 * 4) * 4,
                  Bg + (size_t)r * K + k0 + k4 * 4);
        }
        asm volatile("cp.async.commit_group;");
    };

    const int NT = K / 32;
    load_tile(0, 0);

    for (int t = 0; t < NT; t++) {
        const int p = t & 1;
        if (t + 1 < NT) {
            load_tile(t + 1, p ^ 1);
            asm volatile("cp.async.wait_group 1;");
        } else {
            asm volatile("cp.async.wait_group 0;");
        }
        __syncthreads();

        const float* Ab = Asm[p];
        const float* Bb = Bsm[p];
#pragma unroll
        for (int ks = 0; ks < 4; ks++) {
            const int k0 = ks * 8 + tg;
            uint32_t a[4][4], b[8][2];
#pragma unroll
            for (int mf = 0; mf < 4; mf++) {
                int m = wm * 64 + mf * 16 + g;
                a[mf][0] = __float_as_uint(Ab[m * MG_ASTRIDE + k0]);
                a[mf][1] = __float_as_uint(Ab[(m + 8) * MG_ASTRIDE + k0]);
                a[mf][2] = __float_as_uint(Ab[m * MG_ASTRIDE + k0 + 4]);
                a[mf][3] = __float_as_uint(Ab[(m + 8) * MG_ASTRIDE + k0 + 4]);
            }
#pragma unroll
            for (int nf = 0; nf < 8; nf++) {
                int n = wn * 64 + nf * 8 + g;
                b[nf][0] = __float_as_uint(Bb[n * MG_ASTRIDE + k0]);
                b[nf][1] = __float_as_uint(Bb[n * MG_ASTRIDE + k0 + 4]);
            }
#pragma unroll
            for (int mf = 0; mf < 4; mf++)
#pragma unroll
                for (int nf = 0; nf < 8; nf++)
                    mma_tf32(acc[mf][nf],
                             a[mf][0], a[mf][1], a[mf][2], a[mf][3],
                             b[nf][0], b[nf][1]);
        }
        __syncthreads();
    }

    float* Cb = C + bz * sC;
#pragma unroll
    for (int mf = 0; mf < 4; mf++) {
        const int r0 = bm + wm * 64 + mf * 16 + g;
        const int r1 = r0 + 8;
#pragma unroll
        for (int nf = 0; nf < 8; nf++) {
            const int c = bn + wn * 64 + nf * 8 + tg * 2;
            *reinterpret_cast<float2*>(&Cb[(size_t)r0 * ldc + c]) =
                make_float2(acc[mf][nf][0], acc[mf][nf][1]);
            *reinterpret_cast<float2*>(&Cb[(size_t)r1 * ldc + c]) =
                make_float2(acc[mf][nf][2], acc[mf][nf][3]);
        }
    }
}

// ============================================================================
// fp32 split-tile SGEMM.
//   EXP:  epilogue applies rntf32(__expf(.)) (P must be tf32-exact)
//   RSUM: epilogue also emits per-block column sums into rsp
//         (deterministic smem reduction; layout rsp[b][blockY][N])
// Epilogue stores are float4 (cols tn0..tn0+3 / BN/2+tn0..+3 contiguous).
// ============================================================================
template <int BM, int BN, int BK, int TM, int TN, bool AT, bool EXP, bool RSUM>
__global__ void __launch_bounds__((BM / TM) * (BN / TN))
sgemm_tpl(const float* __restrict__ A, const float* __restrict__ B,
          float* __restrict__ C, int M, int N, int K,
          long long sA, long long sB, long long sC,
          float* __restrict__ rsp)
{
    constexpr int THREADS = (BM / TM) * (BN / TN);
    constexpr int PAD = 4;
    __shared__ float As[BK][BM + PAD];
    __shared__ float Bs[BK][BN];
    __shared__ float red[RSUM ? (16 * BN) : 1];

    const long long bz = blockIdx.z;
    A += bz * sA; B += bz * sB; C += bz * sC;

    const int bm = blockIdx.y * BM;
    const int bn = blockIdx.x * BN;
    const int tid = threadIdx.x;

    constexpr int RX = BN / TN;
    const int tx = tid % RX;
    const int ty = tid / RX;
    const int tn0 = tx * (TN / 2);
    const int tm0 = ty * (TM / 2);

    float acc[TM][TN];
#pragma unroll
    for (int i = 0; i < TM; i++)
#pragma unroll
        for (int j = 0; j < TN; j++) acc[i][j] = 0.f;

    for (int k0 = 0; k0 < K; k0 += BK) {
        if (AT) {
            constexpr int NV = BM * BK / 4;
#pragma unroll
            for (int r = 0; r < NV / THREADS; r++) {
                int i = r * THREADS + tid;
                int kk = i / (BM / 4);
                int mv = i % (BM / 4);
                float4 v = *reinterpret_cast<const float4*>(
                    A + (long long)(k0 + kk) * M + bm + mv * 4);
                As[kk][mv * 4 + 0] = v.x; As[kk][mv * 4 + 1] = v.y;
                As[kk][mv * 4 + 2] = v.z; As[kk][mv * 4 + 3] = v.w;
            }
        } else {
            constexpr int NE = BM * BK;
#pragma unroll
            for (int r = 0; r < NE / THREADS; r++) {
                int i = r * THREADS + tid;
                int mm = i / BK;
                int kk = i % BK;
                As[kk][mm] = A[(long long)(bm + mm) * K + k0 + kk];
            }
        }
        constexpr int NBV = BK * BN / 4;
#pragma unroll
        for (int r = 0; r < NBV / THREADS; r++) {
            int i = r * THREADS + tid;
            int kk = i / (BN / 4);
            int nv = i % (BN / 4);
            float4 v = *reinterpret_cast<const float4*>(
                B + (long long)(k0 + kk) * N + bn + nv * 4);
            *reinterpret_cast<float4*>(&Bs[kk][nv * 4]) = v;
        }
        __syncthreads();

#pragma unroll
        for (int kk = 0; kk < BK; kk++) {
            float ar[TM], br[TN];
#pragma unroll
            for (int i = 0; i < TM / 2; i++) {
                ar[i]          = As[kk][tm0 + i];
                ar[TM / 2 + i] = As[kk][BM / 2 + tm0 + i];
            }
#pragma unroll
            for (int j = 0; j < TN / 2; j++) {
                br[j]          = Bs[kk][tn0 + j];
                br[TN / 2 + j] = Bs[kk][BN / 2 + tn0 + j];
            }
#pragma unroll
            for (int i = 0; i < TM; i++)
#pragma unroll
                for (int j = 0; j < TN; j++)
                    acc[i][j] = fmaf(ar[i], br[j], acc[i][j]);
        }
        __syncthreads();
    }

    // ---- epilogue: float4 stores (+ optional column-sum collection) ----
    float cs[TN];
    if (RSUM) {
#pragma unroll
        for (int j = 0; j < TN; j++) cs[j] = 0.f;
    }
#pragma unroll
    for (int i = 0; i < TM; i++) {
        int row = bm + ((i < TM / 2) ? (tm0 + i) : (BM / 2 + tm0 + i - TM / 2));
        float* Cr = C + (long long)row * N + bn;
        float4 v0, v1;
        {
            float e0 = acc[i][0], e1 = acc[i][1], e2 = acc[i][2], e3 = acc[i][3];
            if (EXP) {
                e0 = rntf32(__expf(e0)); e1 = rntf32(__expf(e1));
                e2 = rntf32(__expf(e2)); e3 = rntf32(__expf(e3));
            }
            if (RSUM) { cs[0] += e0; cs[1] += e1; cs[2] += e2; cs[3] += e3; }
            v0 = make_float4(e0, e1, e2, e3);
        }
        {
            float e0 = acc[i][4], e1 = acc[i][5], e2 = acc[i][6], e3 = acc[i][7];
            if (EXP) {
                e0 = rntf32(__expf(e0)); e1 = rntf32(__expf(e1));
                e2 = rntf32(__expf(e2)); e3 = rntf32(__expf(e3));
            }
            if (RSUM) { cs[4] += e0; cs[5] += e1; cs[6] += e2; cs[7] += e3; }
            v1 = make_float4(e0, e1, e2, e3);
        }
        *reinterpret_cast<float4*>(&Cr[tn0])          = v0;
        *reinterpret_cast<float4*>(&Cr[BN / 2 + tn0]) = v1;
    }

    if (RSUM) {
        // red[ty][col]: each thread owns 8 distinct cols -> written exactly once
        *reinterpret_cast<float4*>(&red[ty * BN + tn0]) =
            make_float4(cs[0], cs[1], cs[2], cs[3]);
        *reinterpret_cast<float4*>(&red[ty * BN + BN / 2 + tn0]) =
            make_float4(cs[4], cs[5], cs[6], cs[7]);
        __syncthreads();
        if (tid < BN) {
            float s = 0.f;
#pragma unroll
            for (int t = 0; t < 16; t++) s += red[t * BN + tid];
            rsp[((size_t)bz * 32 + blockIdx.y) * NN + bn + tid] = s;
        }
    }
}

// ============================================================================
// x[b][c][n] -> xT[b][n][c], rounded to tf32
// ============================================================================
__global__ void transpose_k(const float* __restrict__ x, float* __restrict__ xT)
{
    __shared__ float t[32][33];
    const size_t base = (size_t)blockIdx.z * CC * NN;
    const int c0 = blockIdx.y * 32;
    const int n0 = blockIdx.x * 32;
    const float* xi = x + base;
    float* xo = xT + base;
#pragma unroll
    for (int i = threadIdx.y; i < 32; i += 8)
        t[i][threadIdx.x] = xi[(size_t)(c0 + i) * NN + n0 + threadIdx.x];
    __syncthreads();
#pragma unroll
    for (int i = threadIdx.y; i < 32; i += 8)
        xo[(size_t)(n0 + i) * CC + c0 + threadIdx.x] = rntf32(t[threadIdx.x][i]);
}

// Wv -> g_Wv rounded to tf32
__global__ void roundw_k(const float* __restrict__ W, float* __restrict__ Wo)
{
    int i = blockIdx.x * 256 + threadIdx.x;
    Wo[i] = rntf32(W[i]);
}

// Concat [Wq; Wk] -> g_Wqk (rows 0-31 = Wq, 32-63 = Wk)
__global__ void concatw_k(const float* __restrict__ Wq, const float* __restrict__ Wk,
                          float* __restrict__ Wo)
{
    int i = blockIdx.x * 256 + threadIdx.x;    // < 32768
    Wo[i] = (i < DD * CC) ? Wq[i] : Wk[i - DD * CC];
}

// Final column-sum reduction: rs[b][m] = sum_j rsp[b][j][m]
__global__ void colsum_final(const float* __restrict__ rsp, float* __restrict__ rs)
{
    const int m = blockIdx.x * 256 + threadIdx.x;
    const int b = blockIdx.y;
    float s = 0.f;
#pragma unroll
    for (int j = 0; j < 32; j++) s += rsp[((size_t)b * 32 + j) * NN + m];
    rs[b * NN + m] = s;
}

// v[b][c][m] = rntf32(v / rs[b][m])
__global__ void vscale_k(float* __restrict__ v, const float* __restrict__ rs)
{
    size_t idx = (size_t)blockIdx.x * blockDim.x + threadIdx.x;
    int m = (int)(idx & (NN - 1));
    int b = (int)(idx >> 21);
    v[idx] = rntf32(v[idx] / rs[b * NN + m]);
}

// ============================================================================
extern "C" void kernel_launch(void* const* d_in, const int* in_sizes, int n_in,
                              void* d_out, int out_size)
{
    const float* x = nullptr;
    const float* Wq = nullptr;
    const float* Wk = nullptr;
    const float* Wv = nullptr;
    for (int i = 0; i < n_in; i++) {
        int sz = in_sizes[i];
        const float* p = (const float*)d_in[i];
        if (sz == BB * CC * NN)      x = p;
        else if (sz == CC * CC)      Wv = p;
        else if (sz == DD * CC) { if (!Wq) Wq = p; else Wk = p; }
    }
    float* out = (float*)d_out;

    float *qk, *v, *xT, *P, *Wvr, *Wqk, *rsp, *rs;
    cudaGetSymbolAddress((void**)&qk,  g_qk);
    cudaGetSymbolAddress((void**)&v,   g_v);
    cudaGetSymbolAddress((void**)&xT,  g_xT);
    cudaGetSymbolAddress((void**)&P,   g_P);
    cudaGetSymbolAddress((void**)&Wvr, g_Wv);
    cudaGetSymbolAddress((void**)&Wqk, g_Wqk);
    cudaGetSymbolAddress((void**)&rsp, g_rsp);
    cudaGetSymbolAddress((void**)&rs,  g_rs);

    cudaFuncSetAttribute(mma_gemm, cudaFuncAttributeMaxDynamicSharedMemorySize,
                         MG_SMEM_BYTES);

    const long long sX  = (long long)CC * NN;    // x / xT / v batch stride
    const long long sQK = (long long)2 * DD * NN; // qk batch stride
    const long long sP  = (long long)NN * NN;     // P batch stride

    // 0) weight prep
    roundw_k<<<(CC * CC) / 256, 256>>>(Wv, Wvr);
    concatw_k<<<(2 * DD * CC) / 256, 256>>>(Wq, Wk, Wqk);

    // 1) xT = transpose(x) per batch, tf32-rounded: [n][c]
    transpose_k<<<dim3(NN / 32, CC / 32, BB), dim3(32, 8)>>>(x, xT);

    // 2) v[c][m] = sum_ch Wv[c][ch] * xT[m][ch]   (tf32 mma.sync)
    mma_gemm<<<dim3(NN / 256, CC / 128, BB), 256, MG_SMEM_BYTES>>>(
        Wvr, xT, v, CC, 0, sX, sX, NN);

    // 3) qk = [Wq; Wk] @ x   (fp32, one pass over x; [64][n] per batch)
    sgemm_tpl<64, 128, 8, 4, 8, false, false, false>
        <<<dim3(NN / 128, 1, BB), 256>>>(Wqk, x, qk, 2 * DD, NN, CC, 0, sX, sQK, nullptr);

    // 4) P'[n][m] = exp(sum_d k[d][n] q[d][m])  (fp32 AT; tf32-rounded out;
    //    per-block column partials -> rsp fused in the epilogue)
    sgemm_tpl<128, 128, 8, 8, 8, true, true, true>
        <<<dim3(NN / 128, NN / 128, BB), 256>>>(
            qk + (size_t)DD * NN, qk, P, NN, NN, DD, sQK, sQK, sP, rsp);

    // 5) finish rowsums, fold 1/rowsum into v (tf32-rounded)
    colsum_final<<<dim3(NN / 256, BB), 256>>>(rsp, rs);
    vscale_k<<<((size_t)BB * CC * NN) / 256, 256>>>(v, rs);

    // 6) out[c][n] = sum_m v[c][m] * P'[n][m]   (tf32 mma.sync)
    mma_gemm<<<dim3(NN / 256, CC / 128, BB), 256, MG_SMEM_BYTES>>>(
        v, P, out, NN, sX, sP, sX, NN);
}

// round 11
// speedup vs baseline: 2.6964x; 1.1105x over previous
#include <cuda_runtime.h>
#include <cstdint>
#include <math.h>

// Problem constants
#define BB 8
#define CC 512
#define NN 4096   // H*W
#define DD 32     // C / R

// Scratch (allocation-free rule: __device__ globals)
__device__ float g_qk[BB * 2 * DD * NN];               // [b][64][n]: rows 0-31=q, 32-63=k
__device__ float g_v [(size_t)BB * CC * NN];           // v[b][c][m]  64 MB
__device__ float g_xT[(size_t)BB * CC * NN];           // xT[b][n][c] 64 MB (tf32-rounded)
__device__ float g_P [(size_t)BB * NN * NN];           // P'[b][n][m] 512 MB (tf32-rounded)
__device__ float g_Wv[CC * CC];                        // Wv tf32-rounded
__device__ float g_Wqk[2 * DD * CC];                   // concat [Wq; Wk]
__device__ float g_rsp[BB * 32 * NN];                  // partial column sums
__device__ float g_rs [BB * NN];                       // rowsum[b][m]

// ============================================================================
// helpers
// ============================================================================
__device__ __forceinline__ uint32_t smem_u32(const void* p) {
    uint32_t a;
    asm("{ .reg .u64 t; cvta.to.shared.u64 t, %1; cvt.u32.u64 %0, t; }"
        : "=r"(a) : "l"(p));
    return a;
}
__device__ __forceinline__ void cpa16(uint32_t dst, const void* src) {
    asm volatile("cp.async.cg.shared.global [%0], [%1], 16;"
                 :: "r"(dst), "l"(src));
}
__device__ __forceinline__ float rntf32(float f) {
    uint32_t u;
    asm("cvt.rna.tf32.f32 %0, %1;" : "=r"(u) : "f"(f));
    return __uint_as_float(u);
}
__device__ __forceinline__ void mma_tf32(float c[4],
                                         uint32_t a0, uint32_t a1, uint32_t a2, uint32_t a3,
                                         uint32_t b0, uint32_t b1) {
    asm volatile(
        "mma.sync.aligned.m16n8k8.row.col.f32.tf32.tf32.f32 "
        "{%0,%1,%2,%3}, {%4,%5,%6,%7}, {%8,%9}, {%0,%1,%2,%3};"
        : "+f"(c[0]), "+f"(c[1]), "+f"(c[2]), "+f"(c[3])
        : "r"(a0), "r"(a1), "r"(a2), "r"(a3), "r"(b0), "r"(b1));
}

// ============================================================================
// tf32 mma.sync GEMM: C[m][n] = sum_k A[m][k] * B[n][k]
// Block tile 128(M) x 256(N) x 32(K); 8 warps, each 64x64.
// 3-stage cp.async pipeline + fragment ping-pong (LDS of ks+1 under MMA of ks).
// One __syncthreads per K-tile.
// ============================================================================
#define MG_ASTRIDE 36
#define MG_ASZ (128 * MG_ASTRIDE)
#define MG_BSZ (256 * MG_ASTRIDE)
#define MG_STAGES 3
#define MG_STAGE_FLOATS (MG_ASZ + MG_BSZ)
#define MG_SMEM_BYTES (MG_STAGES * MG_STAGE_FLOATS * 4)   // 165888

__global__ void __launch_bounds__(256)
mma_gemm(const float* __restrict__ A, const float* __restrict__ B,
         float* __restrict__ C, int K,
         long long sA, long long sB, long long sC, int ldc)
{
    extern __shared__ float sm[];
    const uint32_t sb = smem_u32(sm);

    const int tid = threadIdx.x;
    const int lane = tid & 31;
    const int wid = tid >> 5;
    const int g = lane >> 2;
    const int tg = lane & 3;
    const int wm = wid & 1;
    const int wn = wid >> 1;

    const long long bz = blockIdx.z;
    const int bm = blockIdx.y * 128;
    const int bn = blockIdx.x * 256;
    const float* Ag = A + bz * sA + (size_t)bm * K;
    const float* Bg = B + bz * sB + (size_t)bn * K;

    float acc[4][8][4];
#pragma unroll
    for (int mf = 0; mf < 4; mf++)
#pragma unroll
        for (int nf = 0; nf < 8; nf++)
#pragma unroll
            for (int i = 0; i < 4; i++) acc[mf][nf][i] = 0.f;

    const int row = tid >> 3;
    const int k4  = tid & 7;

    auto load_tile = [&](int t, int s) {
        const int k0 = t * 32;
        const uint32_t abase = sb + (uint32_t)(s * MG_STAGE_FLOATS) * 4;
        const uint32_t bbase = abase + (uint32_t)MG_ASZ * 4;
#pragma unroll
        for (int it = 0; it < 4; it++) {
            int r = it * 32 + row;
            cpa16(abase + (uint32_t)(r * MG_ASTRIDE + k4 * 4) * 4,
                  Ag + (size_t)r * K + k0 + k4 * 4);
        }
#pragma unroll
        for (int it = 0; it < 8; it++) {
            int r = it * 32 + row;
            cpa16(bbase + (uint32_t)(r * MG_ASTRIDE + k4 * 4) * 4,
                  Bg + (size_t)r * K + k0 + k4 * 4);
        }
        asm volatile("cp.async.commit_group;");
    };

    const int NT = K / 32;

    load_tile(0, 0);
    load_tile(1, 1);

    uint32_t af[2][4][4], bf[2][8][2];

    for (int t = 0; t < NT; t++) {
        const int s = t % MG_STAGES;
        // Ensure stage s (group t) is complete. At most group t+1 may stay pending.
        if (t + 1 < NT) asm volatile("cp.async.wait_group 1;");
        else            asm volatile("cp.async.wait_group 0;");
        __syncthreads();   // stage-t data visible to all; all done reading stage (t-1)%3

        if (t + 2 < NT) load_tile(t + 2, (t + 2) % MG_STAGES);

        const float* Ab = sm + s * MG_STAGE_FLOATS;
        const float* Bb = Ab + MG_ASZ;

        // Fragment prefetch for ks=0
        {
            const int k0 = tg;
#pragma unroll
            for (int mf = 0; mf < 4; mf++) {
                int m = wm * 64 + mf * 16 + g;
                af[0][mf][0] = __float_as_uint(Ab[m * MG_ASTRIDE + k0]);
                af[0][mf][1] = __float_as_uint(Ab[(m + 8) * MG_ASTRIDE + k0]);
                af[0][mf][2] = __float_as_uint(Ab[m * MG_ASTRIDE + k0 + 4]);
                af[0][mf][3] = __float_as_uint(Ab[(m + 8) * MG_ASTRIDE + k0 + 4]);
            }
#pragma unroll
            for (int nf = 0; nf < 8; nf++) {
                int n = wn * 64 + nf * 8 + g;
                bf[0][nf][0] = __float_as_uint(Bb[n * MG_ASTRIDE + k0]);
                bf[0][nf][1] = __float_as_uint(Bb[n * MG_ASTRIDE + k0 + 4]);
            }
        }

#pragma unroll
        for (int ks = 0; ks < 4; ks++) {
            const int cur = ks & 1;
            const int nxt = cur ^ 1;
            if (ks < 3) {
                const int k0 = (ks + 1) * 8 + tg;
#pragma unroll
                for (int mf = 0; mf < 4; mf++) {
                    int m = wm * 64 + mf * 16 + g;
                    af[nxt][mf][0] = __float_as_uint(Ab[m * MG_ASTRIDE + k0]);
                    af[nxt][mf][1] = __float_as_uint(Ab[(m + 8) * MG_ASTRIDE + k0]);
                    af[nxt][mf][2] = __float_as_uint(Ab[m * MG_ASTRIDE + k0 + 4]);
                    af[nxt][mf][3] = __float_as_uint(Ab[(m + 8) * MG_ASTRIDE + k0 + 4]);
                }
#pragma unroll
                for (int nf = 0; nf < 8; nf++) {
                    int n = wn * 64 + nf * 8 + g;
                    bf[nxt][nf][0] = __float_as_uint(Bb[n * MG_ASTRIDE + k0]);
                    bf[nxt][nf][1] = __float_as_uint(Bb[n * MG_ASTRIDE + k0 + 4]);
                }
            }
#pragma unroll
            for (int mf = 0; mf < 4; mf++)
#pragma unroll
                for (int nf = 0; nf < 8; nf++)
                    mma_tf32(acc[mf][nf],
                             af[cur][mf][0], af[cur][mf][1],
                             af[cur][mf][2], af[cur][mf][3],
                             bf[cur][nf][0], bf[cur][nf][1]);
        }
    }

    float* Cb = C + bz * sC;
#pragma unroll
    for (int mf = 0; mf < 4; mf++) {
        const int r0 = bm + wm * 64 + mf * 16 + g;
        const int r1 = r0 + 8;
#pragma unroll
        for (int nf = 0; nf < 8; nf++) {
            const int c = bn + wn * 64 + nf * 8 + tg * 2;
            *reinterpret_cast<float2*>(&Cb[(size_t)r0 * ldc + c]) =
                make_float2(acc[mf][nf][0], acc[mf][nf][1]);
            *reinterpret_cast<float2*>(&Cb[(size_t)r1 * ldc + c]) =
                make_float2(acc[mf][nf][2], acc[mf][nf][3]);
        }
    }
}

// ============================================================================
// fp32 split-tile SGEMM.
//   EXP:  epilogue applies rntf32(__expf(.)) (P must be tf32-exact)
//   RSUM: epilogue also emits per-block column sums into rsp
// ============================================================================
template <int BM, int BN, int BK, int TM, int TN, bool AT, bool EXP, bool RSUM>
__global__ void __launch_bounds__((BM / TM) * (BN / TN))
sgemm_tpl(const float* __restrict__ A, const float* __restrict__ B,
          float* __restrict__ C, int M, int N, int K,
          long long sA, long long sB, long long sC,
          float* __restrict__ rsp)
{
    constexpr int THREADS = (BM / TM) * (BN / TN);
    constexpr int PAD = 4;
    __shared__ float As[BK][BM + PAD];
    __shared__ float Bs[BK][BN];
    __shared__ float red[RSUM ? (16 * BN) : 1];

    const long long bz = blockIdx.z;
    A += bz * sA; B += bz * sB; C += bz * sC;

    const int bm = blockIdx.y * BM;
    const int bn = blockIdx.x * BN;
    const int tid = threadIdx.x;

    constexpr int RX = BN / TN;
    const int tx = tid % RX;
    const int ty = tid / RX;
    const int tn0 = tx * (TN / 2);
    const int tm0 = ty * (TM / 2);

    float acc[TM][TN];
#pragma unroll
    for (int i = 0; i < TM; i++)
#pragma unroll
        for (int j = 0; j < TN; j++) acc[i][j] = 0.f;

    for (int k0 = 0; k0 < K; k0 += BK) {
        if (AT) {
            constexpr int NV = BM * BK / 4;
#pragma unroll
            for (int r = 0; r < NV / THREADS; r++) {
                int i = r * THREADS + tid;
                int kk = i / (BM / 4);
                int mv = i % (BM / 4);
                float4 v = *reinterpret_cast<const float4*>(
                    A + (long long)(k0 + kk) * M + bm + mv * 4);
                As[kk][mv * 4 + 0] = v.x; As[kk][mv * 4 + 1] = v.y;
                As[kk][mv * 4 + 2] = v.z; As[kk][mv * 4 + 3] = v.w;
            }
        } else {
            constexpr int NE = BM * BK;
#pragma unroll
            for (int r = 0; r < NE / THREADS; r++) {
                int i = r * THREADS + tid;
                int mm = i / BK;
                int kk = i % BK;
                As[kk][mm] = A[(long long)(bm + mm) * K + k0 + kk];
            }
        }
        constexpr int NBV = BK * BN / 4;
#pragma unroll
        for (int r = 0; r < NBV / THREADS; r++) {
            int i = r * THREADS + tid;
            int kk = i / (BN / 4);
            int nv = i % (BN / 4);
            float4 v = *reinterpret_cast<const float4*>(
                B + (long long)(k0 + kk) * N + bn + nv * 4);
            *reinterpret_cast<float4*>(&Bs[kk][nv * 4]) = v;
        }
        __syncthreads();

#pragma unroll
        for (int kk = 0; kk < BK; kk++) {
            float ar[TM], br[TN];
#pragma unroll
            for (int i = 0; i < TM / 2; i++) {
                ar[i]          = As[kk][tm0 + i];
                ar[TM / 2 + i] = As[kk][BM / 2 + tm0 + i];
            }
#pragma unroll
            for (int j = 0; j < TN / 2; j++) {
                br[j]          = Bs[kk][tn0 + j];
                br[TN / 2 + j] = Bs[kk][BN / 2 + tn0 + j];
            }
#pragma unroll
            for (int i = 0; i < TM; i++)
#pragma unroll
                for (int j = 0; j < TN; j++)
                    acc[i][j] = fmaf(ar[i], br[j], acc[i][j]);
        }
        __syncthreads();
    }

    float cs[TN];
    if (RSUM) {
#pragma unroll
        for (int j = 0; j < TN; j++) cs[j] = 0.f;
    }
#pragma unroll
    for (int i = 0; i < TM; i++) {
        int row = bm + ((i < TM / 2) ? (tm0 + i) : (BM / 2 + tm0 + i - TM / 2));
        float* Cr = C + (long long)row * N + bn;
        float4 v0, v1;
        {
            float e0 = acc[i][0], e1 = acc[i][1], e2 = acc[i][2], e3 = acc[i][3];
            if (EXP) {
                e0 = rntf32(__expf(e0)); e1 = rntf32(__expf(e1));
                e2 = rntf32(__expf(e2)); e3 = rntf32(__expf(e3));
            }
            if (RSUM) { cs[0] += e0; cs[1] += e1; cs[2] += e2; cs[3] += e3; }
            v0 = make_float4(e0, e1, e2, e3);
        }
        {
            float e0 = acc[i][4], e1 = acc[i][5], e2 = acc[i][6], e3 = acc[i][7];
            if (EXP) {
                e0 = rntf32(__expf(e0)); e1 = rntf32(__expf(e1));
                e2 = rntf32(__expf(e2)); e3 = rntf32(__expf(e3));
            }
            if (RSUM) { cs[4] += e0; cs[5] += e1; cs[6] += e2; cs[7] += e3; }
            v1 = make_float4(e0, e1, e2, e3);
        }
        *reinterpret_cast<float4*>(&Cr[tn0])          = v0;
        *reinterpret_cast<float4*>(&Cr[BN / 2 + tn0]) = v1;
    }

    if (RSUM) {
        *reinterpret_cast<float4*>(&red[ty * BN + tn0]) =
            make_float4(cs[0], cs[1], cs[2], cs[3]);
        *reinterpret_cast<float4*>(&red[ty * BN + BN / 2 + tn0]) =
            make_float4(cs[4], cs[5], cs[6], cs[7]);
        __syncthreads();
        if (tid < BN) {
            float s = 0.f;
#pragma unroll
            for (int t = 0; t < 16; t++) s += red[t * BN + tid];
            rsp[((size_t)bz * 32 + blockIdx.y) * NN + bn + tid] = s;
        }
    }
}

// ============================================================================
// x[b][c][n] -> xT[b][n][c], rounded to tf32
// ============================================================================
__global__ void transpose_k(const float* __restrict__ x, float* __restrict__ xT)
{
    __shared__ float t[32][33];
    const size_t base = (size_t)blockIdx.z * CC * NN;
    const int c0 = blockIdx.y * 32;
    const int n0 = blockIdx.x * 32;
    const float* xi = x + base;
    float* xo = xT + base;
#pragma unroll
    for (int i = threadIdx.y; i < 32; i += 8)
        t[i][threadIdx.x] = xi[(size_t)(c0 + i) * NN + n0 + threadIdx.x];
    __syncthreads();
#pragma unroll
    for (int i = threadIdx.y; i < 32; i += 8)
        xo[(size_t)(n0 + i) * CC + c0 + threadIdx.x] = rntf32(t[threadIdx.x][i]);
}

// Wv -> g_Wv rounded to tf32
__global__ void roundw_k(const float* __restrict__ W, float* __restrict__ Wo)
{
    int i = blockIdx.x * 256 + threadIdx.x;
    Wo[i] = rntf32(W[i]);
}

// Concat [Wq; Wk] -> g_Wqk
__global__ void concatw_k(const float* __restrict__ Wq, const float* __restrict__ Wk,
                          float* __restrict__ Wo)
{
    int i = blockIdx.x * 256 + threadIdx.x;
    Wo[i] = (i < DD * CC) ? Wq[i] : Wk[i - DD * CC];
}

// Final column-sum reduction: rs[b][m] = sum_j rsp[b][j][m]
__global__ void colsum_final(const float* __restrict__ rsp, float* __restrict__ rs)
{
    const int m = blockIdx.x * 256 + threadIdx.x;
    const int b = blockIdx.y;
    float s = 0.f;
#pragma unroll
    for (int j = 0; j < 32; j++) s += rsp[((size_t)b * 32 + j) * NN + m];
    rs[b * NN + m] = s;
}

// v[b][c][m] = rntf32(v / rs[b][m])
__global__ void vscale_k(float* __restrict__ v, const float* __restrict__ rs)
{
    size_t idx = (size_t)blockIdx.x * blockDim.x + threadIdx.x;
    int m = (int)(idx & (NN - 1));
    int b = (int)(idx >> 21);
    v[idx] = rntf32(v[idx] / rs[b * NN + m]);
}

// ============================================================================
extern "C" void kernel_launch(void* const* d_in, const int* in_sizes, int n_in,
                              void* d_out, int out_size)
{
    const float* x = nullptr;
    const float* Wq = nullptr;
    const float* Wk = nullptr;
    const float* Wv = nullptr;
    for (int i = 0; i < n_in; i++) {
        int sz = in_sizes[i];
        const float* p = (const float*)d_in[i];
        if (sz == BB * CC * NN)      x = p;
        else if (sz == CC * CC)      Wv = p;
        else if (sz == DD * CC) { if (!Wq) Wq = p; else Wk = p; }
    }
    float* out = (float*)d_out;

    float *qk, *v, *xT, *P, *Wvr, *Wqk, *rsp, *rs;
    cudaGetSymbolAddress((void**)&qk,  g_qk);
    cudaGetSymbolAddress((void**)&v,   g_v);
    cudaGetSymbolAddress((void**)&xT,  g_xT);
    cudaGetSymbolAddress((void**)&P,   g_P);
    cudaGetSymbolAddress((void**)&Wvr, g_Wv);
    cudaGetSymbolAddress((void**)&Wqk, g_Wqk);
    cudaGetSymbolAddress((void**)&rsp, g_rsp);
    cudaGetSymbolAddress((void**)&rs,  g_rs);

    cudaFuncSetAttribute(mma_gemm, cudaFuncAttributeMaxDynamicSharedMemorySize,
                         MG_SMEM_BYTES);

    const long long sX  = (long long)CC * NN;
    const long long sQK = (long long)2 * DD * NN;
    const long long sP  = (long long)NN * NN;

    // 0) weight prep
    roundw_k<<<(CC * CC) / 256, 256>>>(Wv, Wvr);
    concatw_k<<<(2 * DD * CC) / 256, 256>>>(Wq, Wk, Wqk);

    // 1) xT = transpose(x) per batch, tf32-rounded
    transpose_k<<<dim3(NN / 32, CC / 32, BB), dim3(32, 8)>>>(x, xT);

    // 2) v[c][m] = Wv @ xT   (tf32 mma.sync)
    mma_gemm<<<dim3(NN / 256, CC / 128, BB), 256, MG_SMEM_BYTES>>>(
        Wvr, xT, v, CC, 0, sX, sX, NN);

    // 3) qk = [Wq; Wk] @ x   (fp32, one pass over x)
    sgemm_tpl<64, 128, 8, 4, 8, false, false, false>
        <<<dim3(NN / 128, 1, BB), 256>>>(Wqk, x, qk, 2 * DD, NN, CC, 0, sX, sQK, nullptr);

    // 4) P'[n][m] = exp(k^T q)  (fp32 AT; tf32-rounded; fused column partials)
    sgemm_tpl<128, 128, 8, 8, 8, true, true, true>
        <<<dim3(NN / 128, NN / 128, BB), 256>>>(
            qk + (size_t)DD * NN, qk, P, NN, NN, DD, sQK, sQK, sP, rsp);

    // 5) finish rowsums, fold 1/rowsum into v
    colsum_final<<<dim3(NN / 256, BB), 256>>>(rsp, rs);
    vscale_k<<<((size_t)BB * CC * NN) / 256, 256>>>(v, rs);

    // 6) out[c][n] = v' @ P   (tf32 mma.sync)
    mma_gemm<<<dim3(NN / 256, CC / 128, BB), 256, MG_SMEM_BYTES>>>(
        v, P, out, NN, sX, sP, sX, NN);
}

// round 12
// speedup vs baseline: 2.7247x; 1.0105x over previous
#include <cuda_runtime.h>
#include <cstdint>
#include <math.h>

// Problem constants
#define BB 8
#define CC 512
#define NN 4096   // H*W
#define DD 32     // C / R

// Scratch (allocation-free rule: __device__ globals)
__device__ float g_qk[BB * 2 * DD * NN];               // [b][64][n]: rows 0-31=q, 32-63=k
__device__ float g_v [(size_t)BB * CC * NN];           // v[b][c][m]  64 MB
__device__ float g_xT[(size_t)BB * CC * NN];           // xT[b][n][c] 64 MB (tf32-rounded)
__device__ float g_P [(size_t)BB * NN * NN];           // P'[b][n][m] 512 MB (tf32-rounded)
__device__ float g_Wv[CC * CC];                        // Wv tf32-rounded
__device__ float g_Wqk[2 * DD * CC];                   // concat [Wq; Wk]
__device__ float g_rsp[BB * 32 * NN];                  // partial column sums
__device__ float g_rs [BB * NN];                       // rowsum[b][m]

// ============================================================================
// helpers
// ============================================================================
__device__ __forceinline__ uint32_t smem_u32(const void* p) {
    uint32_t a;
    asm("{ .reg .u64 t; cvta.to.shared.u64 t, %1; cvt.u32.u64 %0, t; }"
        : "=r"(a) : "l"(p));
    return a;
}
__device__ __forceinline__ void cpa16(uint32_t dst, const void* src) {
    asm volatile("cp.async.cg.shared.global [%0], [%1], 16;"
                 :: "r"(dst), "l"(src));
}
__device__ __forceinline__ float rntf32(float f) {
    uint32_t u;
    asm("cvt.rna.tf32.f32 %0, %1;" : "=r"(u) : "f"(f));
    return __uint_as_float(u);
}
__device__ __forceinline__ void mma_tf32(float c[4],
                                         uint32_t a0, uint32_t a1, uint32_t a2, uint32_t a3,
                                         uint32_t b0, uint32_t b1) {
    asm volatile(
        "mma.sync.aligned.m16n8k8.row.col.f32.tf32.tf32.f32 "
        "{%0,%1,%2,%3}, {%4,%5,%6,%7}, {%8,%9}, {%0,%1,%2,%3};"
        : "+f"(c[0]), "+f"(c[1]), "+f"(c[2]), "+f"(c[3])
        : "r"(a0), "r"(a1), "r"(a2), "r"(a3), "r"(b0), "r"(b1));
}

// ============================================================================
// tf32 mma.sync GEMM: C[m][n] = sum_k A[m][k] * B[n][k]
// Block tile 128(M) x 256(N) x 32(K); 8 warps, each 64x64.
// 3-stage cp.async pipeline + CROSS-TILE fragment ping-pong:
// the next tile's ks=0 fragments are loaded at ks=3 of the current tile,
// right after (load t+2 ; wait_group ; syncthreads), so MMA issue never
// blocks on a post-barrier LDS.
// ============================================================================
#define MG_ASTRIDE 36
#define MG_ASZ (128 * MG_ASTRIDE)
#define MG_BSZ (256 * MG_ASTRIDE)
#define MG_STAGES 3
#define MG_STAGE_FLOATS (MG_ASZ + MG_BSZ)
#define MG_SMEM_BYTES (MG_STAGES * MG_STAGE_FLOATS * 4)   // 165888

__global__ void __launch_bounds__(256)
mma_gemm(const float* __restrict__ A, const float* __restrict__ B,
         float* __restrict__ C, int K,
         long long sA, long long sB, long long sC, int ldc)
{
    extern __shared__ float sm[];
    const uint32_t sb = smem_u32(sm);

    const int tid = threadIdx.x;
    const int lane = tid & 31;
    const int wid = tid >> 5;
    const int g = lane >> 2;
    const int tg = lane & 3;
    const int wm = wid & 1;
    const int wn = wid >> 1;

    const long long bz = blockIdx.z;
    const int bm = blockIdx.y * 128;
    const int bn = blockIdx.x * 256;
    const float* Ag = A + bz * sA + (size_t)bm * K;
    const float* Bg = B + bz * sB + (size_t)bn * K;

    float acc[4][8][4];
#pragma unroll
    for (int mf = 0; mf < 4; mf++)
#pragma unroll
        for (int nf = 0; nf < 8; nf++)
#pragma unroll
            for (int i = 0; i < 4; i++) acc[mf][nf][i] = 0.f;

    const int row = tid >> 3;
    const int k4  = tid & 7;

    auto load_tile = [&](int t) {
        const int s = t % MG_STAGES;
        const int k0 = t * 32;
        const uint32_t abase = sb + (uint32_t)(s * MG_STAGE_FLOATS) * 4;
        const uint32_t bbase = abase + (uint32_t)MG_ASZ * 4;
#pragma unroll
        for (int it = 0; it < 4; it++) {
            int r = it * 32 + row;
            cpa16(abase + (uint32_t)(r * MG_ASTRIDE + k4 * 4) * 4,
                  Ag + (size_t)r * K + k0 + k4 * 4);
        }
#pragma unroll
        for (int it = 0; it < 8; it++) {
            int r = it * 32 + row;
            cpa16(bbase + (uint32_t)(r * MG_ASTRIDE + k4 * 4) * 4,
                  Bg + (size_t)r * K + k0 + k4 * 4);
        }
        asm volatile("cp.async.commit_group;");
    };

    uint32_t af[2][4][4], bf[2][8][2];
    auto frag_load = [&](const float* Ab, const float* Bb, int k0, int slot) {
#pragma unroll
        for (int mf = 0; mf < 4; mf++) {
            int m = wm * 64 + mf * 16 + g;
            af[slot][mf][0] = __float_as_uint(Ab[m * MG_ASTRIDE + k0]);
            af[slot][mf][1] = __float_as_uint(Ab[(m + 8) * MG_ASTRIDE + k0]);
            af[slot][mf][2] = __float_as_uint(Ab[m * MG_ASTRIDE + k0 + 4]);
            af[slot][mf][3] = __float_as_uint(Ab[(m + 8) * MG_ASTRIDE + k0 + 4]);
        }
#pragma unroll
        for (int nf = 0; nf < 8; nf++) {
            int n = wn * 64 + nf * 8 + g;
            bf[slot][nf][0] = __float_as_uint(Bb[n * MG_ASTRIDE + k0]);
            bf[slot][nf][1] = __float_as_uint(Bb[n * MG_ASTRIDE + k0 + 4]);
        }
    };

    const int NT = K / 32;

    // Prologue: two tiles in flight, fragments for tile 0 / ks 0 in regs.
    load_tile(0);
    load_tile(1);
    asm volatile("cp.async.wait_group 1;");
    __syncthreads();
    frag_load(sm, sm + MG_ASZ, tg, 0);

    for (int t = 0; t < NT; t++) {
        const int s = t % MG_STAGES;
        const float* Ab = sm + s * MG_STAGE_FLOATS;
        const float* Bb = Ab + MG_ASZ;

#pragma unroll
        for (int ks = 0; ks < 4; ks++) {
            const int cur = ks & 1;
            const int nxt = cur ^ 1;

            if (ks < 3) {
                // next k-step of the current tile
                frag_load(Ab, Bb, (ks + 1) * 8 + tg, nxt);
            } else if (t + 1 < NT) {
                // Stage handoff:
                // 1) issue tile t+2 into stage (t+2)%3 == (t-1)%3 — its last
                //    readers were fenced by the sync at tile t-1's ks=3.
                // 2) wait so that group t+1 is complete (<=1 pending).
                // 3) syncthreads publishes tile t+1's smem data to all threads
                //    (and fences this tile's stage for its future reuse).
                // 4) load tile t+1 / ks=0 fragments — overlaps ks=3 MMAs below.
                if (t + 2 < NT) {
                    load_tile(t + 2);
                    asm volatile("cp.async.wait_group 1;");
                } else {
                    asm volatile("cp.async.wait_group 0;");
                }
                __syncthreads();
                const float* An = sm + ((t + 1) % MG_STAGES) * MG_STAGE_FLOATS;
                frag_load(An, An + MG_ASZ, tg, nxt);
            }

#pragma unroll
            for (int mf = 0; mf < 4; mf++)
#pragma unroll
                for (int nf = 0; nf < 8; nf++)
                    mma_tf32(acc[mf][nf],
                             af[cur][mf][0], af[cur][mf][1],
                             af[cur][mf][2], af[cur][mf][3],
                             bf[cur][nf][0], bf[cur][nf][1]);
        }
    }

    float* Cb = C + bz * sC;
#pragma unroll
    for (int mf = 0; mf < 4; mf++) {
        const int r0 = bm + wm * 64 + mf * 16 + g;
        const int r1 = r0 + 8;
#pragma unroll
        for (int nf = 0; nf < 8; nf++) {
            const int c = bn + wn * 64 + nf * 8 + tg * 2;
            *reinterpret_cast<float2*>(&Cb[(size_t)r0 * ldc + c]) =
                make_float2(acc[mf][nf][0], acc[mf][nf][1]);
            *reinterpret_cast<float2*>(&Cb[(size_t)r1 * ldc + c]) =
                make_float2(acc[mf][nf][2], acc[mf][nf][3]);
        }
    }
}

// ============================================================================
// fp32 split-tile SGEMM.
//   EXP:  epilogue applies rntf32(__expf(.)) (P must be tf32-exact)
//   RSUM: epilogue also emits per-block column sums into rsp
// ============================================================================
template <int BM, int BN, int BK, int TM, int TN, bool AT, bool EXP, bool RSUM>
__global__ void __launch_bounds__((BM / TM) * (BN / TN))
sgemm_tpl(const float* __restrict__ A, const float* __restrict__ B,
          float* __restrict__ C, int M, int N, int K,
          long long sA, long long sB, long long sC,
          float* __restrict__ rsp)
{
    constexpr int THREADS = (BM / TM) * (BN / TN);
    constexpr int PAD = 4;
    __shared__ float As[BK][BM + PAD];
    __shared__ float Bs[BK][BN];
    __shared__ float red[RSUM ? (16 * BN) : 1];

    const long long bz = blockIdx.z;
    A += bz * sA; B += bz * sB; C += bz * sC;

    const int bm = blockIdx.y * BM;
    const int bn = blockIdx.x * BN;
    const int tid = threadIdx.x;

    constexpr int RX = BN / TN;
    const int tx = tid % RX;
    const int ty = tid / RX;
    const int tn0 = tx * (TN / 2);
    const int tm0 = ty * (TM / 2);

    float acc[TM][TN];
#pragma unroll
    for (int i = 0; i < TM; i++)
#pragma unroll
        for (int j = 0; j < TN; j++) acc[i][j] = 0.f;

    for (int k0 = 0; k0 < K; k0 += BK) {
        if (AT) {
            constexpr int NV = BM * BK / 4;
#pragma unroll
            for (int r = 0; r < NV / THREADS; r++) {
                int i = r * THREADS + tid;
                int kk = i / (BM / 4);
                int mv = i % (BM / 4);
                float4 v = *reinterpret_cast<const float4*>(
                    A + (long long)(k0 + kk) * M + bm + mv * 4);
                As[kk][mv * 4 + 0] = v.x; As[kk][mv * 4 + 1] = v.y;
                As[kk][mv * 4 + 2] = v.z; As[kk][mv * 4 + 3] = v.w;
            }
        } else {
            constexpr int NE = BM * BK;
#pragma unroll
            for (int r = 0; r < NE / THREADS; r++) {
                int i = r * THREADS + tid;
                int mm = i / BK;
                int kk = i % BK;
                As[kk][mm] = A[(long long)(bm + mm) * K + k0 + kk];
            }
        }
        constexpr int NBV = BK * BN / 4;
#pragma unroll
        for (int r = 0; r < NBV / THREADS; r++) {
            int i = r * THREADS + tid;
            int kk = i / (BN / 4);
            int nv = i % (BN / 4);
            float4 v = *reinterpret_cast<const float4*>(
                B + (long long)(k0 + kk) * N + bn + nv * 4);
            *reinterpret_cast<float4*>(&Bs[kk][nv * 4]) = v;
        }
        __syncthreads();

#pragma unroll
        for (int kk = 0; kk < BK; kk++) {
            float ar[TM], br[TN];
#pragma unroll
            for (int i = 0; i < TM / 2; i++) {
                ar[i]          = As[kk][tm0 + i];
                ar[TM / 2 + i] = As[kk][BM / 2 + tm0 + i];
            }
#pragma unroll
            for (int j = 0; j < TN / 2; j++) {
                br[j]          = Bs[kk][tn0 + j];
                br[TN / 2 + j] = Bs[kk][BN / 2 + tn0 + j];
            }
#pragma unroll
            for (int i = 0; i < TM; i++)
#pragma unroll
                for (int j = 0; j < TN; j++)
                    acc[i][j] = fmaf(ar[i], br[j], acc[i][j]);
        }
        __syncthreads();
    }

    float cs[TN];
    if (RSUM) {
#pragma unroll
        for (int j = 0; j < TN; j++) cs[j] = 0.f;
    }
#pragma unroll
    for (int i = 0; i < TM; i++) {
        int row = bm + ((i < TM / 2) ? (tm0 + i) : (BM / 2 + tm0 + i - TM / 2));
        float* Cr = C + (long long)row * N + bn;
        float4 v0, v1;
        {
            float e0 = acc[i][0], e1 = acc[i][1], e2 = acc[i][2], e3 = acc[i][3];
            if (EXP) {
                e0 = rntf32(__expf(e0)); e1 = rntf32(__expf(e1));
                e2 = rntf32(__expf(e2)); e3 = rntf32(__expf(e3));
            }
            if (RSUM) { cs[0] += e0; cs[1] += e1; cs[2] += e2; cs[3] += e3; }
            v0 = make_float4(e0, e1, e2, e3);
        }
        {
            float e0 = acc[i][4], e1 = acc[i][5], e2 = acc[i][6], e3 = acc[i][7];
            if (EXP) {
                e0 = rntf32(__expf(e0)); e1 = rntf32(__expf(e1));
                e2 = rntf32(__expf(e2)); e3 = rntf32(__expf(e3));
            }
            if (RSUM) { cs[4] += e0; cs[5] += e1; cs[6] += e2; cs[7] += e3; }
            v1 = make_float4(e0, e1, e2, e3);
        }
        *reinterpret_cast<float4*>(&Cr[tn0])          = v0;
        *reinterpret_cast<float4*>(&Cr[BN / 2 + tn0]) = v1;
    }

    if (RSUM) {
        *reinterpret_cast<float4*>(&red[ty * BN + tn0]) =
            make_float4(cs[0], cs[1], cs[2], cs[3]);
        *reinterpret_cast<float4*>(&red[ty * BN + BN / 2 + tn0]) =
            make_float4(cs[4], cs[5], cs[6], cs[7]);
        __syncthreads();
        if (tid < BN) {
            float s = 0.f;
#pragma unroll
            for (int t = 0; t < 16; t++) s += red[t * BN + tid];
            rsp[((size_t)bz * 32 + blockIdx.y) * NN + bn + tid] = s;
        }
    }
}

// ============================================================================
// x[b][c][n] -> xT[b][n][c], rounded to tf32
// ============================================================================
__global__ void transpose_k(const float* __restrict__ x, float* __restrict__ xT)
{
    __shared__ float t[32][33];
    const size_t base = (size_t)blockIdx.z * CC * NN;
    const int c0 = blockIdx.y * 32;
    const int n0 = blockIdx.x * 32;
    const float* xi = x + base;
    float* xo = xT + base;
#pragma unroll
    for (int i = threadIdx.y; i < 32; i += 8)
        t[i][threadIdx.x] = xi[(size_t)(c0 + i) * NN + n0 + threadIdx.x];
    __syncthreads();
#pragma unroll
    for (int i = threadIdx.y; i < 32; i += 8)
        xo[(size_t)(n0 + i) * CC + c0 + threadIdx.x] = rntf32(t[threadIdx.x][i]);
}

// Wv -> g_Wv rounded to tf32
__global__ void roundw_k(const float* __restrict__ W, float* __restrict__ Wo)
{
    int i = blockIdx.x * 256 + threadIdx.x;
    Wo[i] = rntf32(W[i]);
}

// Concat [Wq; Wk] -> g_Wqk
__global__ void concatw_k(const float* __restrict__ Wq, const float* __restrict__ Wk,
                          float* __restrict__ Wo)
{
    int i = blockIdx.x * 256 + threadIdx.x;
    Wo[i] = (i < DD * CC) ? Wq[i] : Wk[i - DD * CC];
}

// Final column-sum reduction: rs[b][m] = sum_j rsp[b][j][m]
__global__ void colsum_final(const float* __restrict__ rsp, float* __restrict__ rs)
{
    const int m = blockIdx.x * 256 + threadIdx.x;
    const int b = blockIdx.y;
    float s = 0.f;
#pragma unroll
    for (int j = 0; j < 32; j++) s += rsp[((size_t)b * 32 + j) * NN + m];
    rs[b * NN + m] = s;
}

// v[b][c][m] = rntf32(v / rs[b][m])
__global__ void vscale_k(float* __restrict__ v, const float* __restrict__ rs)
{
    size_t idx = (size_t)blockIdx.x * blockDim.x + threadIdx.x;
    int m = (int)(idx & (NN - 1));
    int b = (int)(idx >> 21);
    v[idx] = rntf32(v[idx] / rs[b * NN + m]);
}

// ============================================================================
extern "C" void kernel_launch(void* const* d_in, const int* in_sizes, int n_in,
                              void* d_out, int out_size)
{
    const float* x = nullptr;
    const float* Wq = nullptr;
    const float* Wk = nullptr;
    const float* Wv = nullptr;
    for (int i = 0; i < n_in; i++) {
        int sz = in_sizes[i];
        const float* p = (const float*)d_in[i];
        if (sz == BB * CC * NN)      x = p;
        else if (sz == CC * CC)      Wv = p;
        else if (sz == DD * CC) { if (!Wq) Wq = p; else Wk = p; }
    }
    float* out = (float*)d_out;

    float *qk, *v, *xT, *P, *Wvr, *Wqk, *rsp, *rs;
    cudaGetSymbolAddress((void**)&qk,  g_qk);
    cudaGetSymbolAddress((void**)&v,   g_v);
    cudaGetSymbolAddress((void**)&xT,  g_xT);
    cudaGetSymbolAddress((void**)&P,   g_P);
    cudaGetSymbolAddress((void**)&Wvr, g_Wv);
    cudaGetSymbolAddress((void**)&Wqk, g_Wqk);
    cudaGetSymbolAddress((void**)&rsp, g_rsp);
    cudaGetSymbolAddress((void**)&rs,  g_rs);

    cudaFuncSetAttribute(mma_gemm, cudaFuncAttributeMaxDynamicSharedMemorySize,
                         MG_SMEM_BYTES);

    const long long sX  = (long long)CC * NN;
    const long long sQK = (long long)2 * DD * NN;
    const long long sP  = (long long)NN * NN;

    // 0) weight prep
    roundw_k<<<(CC * CC) / 256, 256>>>(Wv, Wvr);
    concatw_k<<<(2 * DD * CC) / 256, 256>>>(Wq, Wk, Wqk);

    // 1) xT = transpose(x) per batch, tf32-rounded
    transpose_k<<<dim3(NN / 32, CC / 32, BB), dim3(32, 8)>>>(x, xT);

    // 2) v[c][m] = Wv @ xT   (tf32 mma.sync)
    mma_gemm<<<dim3(NN / 256, CC / 128, BB), 256, MG_SMEM_BYTES>>>(
        Wvr, xT, v, CC, 0, sX, sX, NN);

    // 3) qk = [Wq; Wk] @ x   (fp32, one pass over x)
    sgemm_tpl<64, 128, 8, 4, 8, false, false, false>
        <<<dim3(NN / 128, 1, BB), 256>>>(Wqk, x, qk, 2 * DD, NN, CC, 0, sX, sQK, nullptr);

    // 4) P'[n][m] = exp(k^T q)  (fp32 AT; tf32-rounded; fused column partials)
    sgemm_tpl<128, 128, 8, 8, 8, true, true, true>
        <<<dim3(NN / 128, NN / 128, BB), 256>>>(
            qk + (size_t)DD * NN, qk, P, NN, NN, DD, sQK, sQK, sP, rsp);

    // 5) finish rowsums, fold 1/rowsum into v
    colsum_final<<<dim3(NN / 256, BB), 256>>>(rsp, rs);
    vscale_k<<<((size_t)BB * CC * NN) / 256, 256>>>(v, rs);

    // 6) out[c][n] = v' @ P   (tf32 mma.sync)
    mma_gemm<<<dim3(NN / 256, CC / 128, BB), 256, MG_SMEM_BYTES>>>(
        v, P, out, NN, sX, sP, sX, NN);
}